// round 1
// baseline (speedup 1.0000x reference)
#include <cuda_runtime.h>

// CIN forward, fused 3 layers.
// B=2048, F0=39, D=16, S=128 per layer. Output (2048, 256) = sum over d of
// concat([relu0[:,64:], relu1[:,64:], relu2[:,0:128]]).
//
// CTA = 64 (b,d) pairs = 4 complete b's (all 16 d's inside one CTA -> local d-sum).
// 8 warps, each warp owns 8 pairs; 32 lanes span the 128 s-outputs (4 each).
// Accumulators packed along m (f32x2), W duplicated into both halves per k.

#define F0 39
#define DH 16
#define SW 128
#define MTILE 64
#define NT 256

__device__ __forceinline__ unsigned long long pkdup(float v) {
    unsigned long long r;
    asm("mov.b64 %0, {%1, %1};" : "=l"(r) : "f"(v));
    return r;
}
__device__ __forceinline__ void fma2(unsigned long long& d,
                                     unsigned long long a,
                                     unsigned long long b) {
    asm("fma.rn.f32x2 %0, %1, %2, %0;" : "+l"(d) : "l"(a), "l"(b));
}
__device__ __forceinline__ float2 upk(unsigned long long v) {
    float2 r;
    asm("mov.b64 {%0, %1}, %2;" : "=f"(r.x), "=f"(r.y) : "l"(v));
    return r;
}

__global__ __launch_bounds__(NT, 2) void cin_kernel(
    const float* __restrict__ x,
    const float* __restrict__ W0, const float* __restrict__ W1,
    const float* __restrict__ W2,
    const float* __restrict__ b0, const float* __restrict__ b1,
    const float* __restrict__ b2,
    float* __restrict__ out)
{
    __shared__ float xs[MTILE][F0 + 2];   // [m][f], padded stride 41 (odd) -> conflict-free column reads
    __shared__ float hs[MTILE][65];       // [m][g], padded stride 65
    __shared__ float ps[F0][MTILE];       // p-tile for current g: ps[f][m], m contiguous
    __shared__ float osum[4][256];        // per-b-local output accumulator

    const int tid   = threadIdx.x;
    const int lane  = tid & 31;
    const int w     = tid >> 5;
    const int mbase = w * 8;          // warp's 8 pairs
    const int s0    = lane * 4;       // lane's 4 s-columns
    const int pair0 = blockIdx.x * MTILE;
    const int b_loc = w >> 1;         // warp's b within CTA (8 pairs share one b)

    // zero output accumulator
    for (int i = tid; i < 4 * 256; i += NT) ((float*)osum)[i] = 0.0f;

    // load x tile: pair = pair0+m, b = pair/16, d = pair%16 ; x[(b*39 + f)*16 + d]
    for (int i = tid; i < MTILE * F0; i += NT) {
        int m = i & (MTILE - 1);
        int f = i >> 6;
        int pair = pair0 + m;
        int b = pair >> 4, d = pair & 15;
        xs[m][f] = x[(size_t)b * (F0 * DH) + f * DH + d];
    }
    __syncthreads();

    const float* Ws[3] = {W0, W1, W2};
    const float* bs[3] = {b0, b1, b2};

    for (int layer = 0; layer < 3; ++layer) {
        const int Fk = (layer == 0) ? F0 : 64;
        const float* __restrict__ Wl = Ws[layer];

        unsigned long long acc[4][4];   // [m-pair][s] packed along m
        #pragma unroll
        for (int i = 0; i < 4; ++i)
            #pragma unroll
            for (int j = 0; j < 4; ++j) acc[i][j] = 0ull;

        for (int g = 0; g < Fk; ++g) {
            __syncthreads();   // protect ps overwrite vs prior reads; hs reads vs prior writes
            // p-phase: ps[f][m] = x[m,f] * h[m,g]
            for (int i = tid; i < F0 * MTILE; i += NT) {
                int m = i & (MTILE - 1);
                int f = i >> 6;
                float hv = (layer == 0) ? xs[m][g] : hs[m][g];
                ps[f][m] = xs[m][f] * hv;
            }
            __syncthreads();

            const float* wp = Wl + (size_t)g * SW + s0;
            const size_t wstride = (size_t)Fk * SW;

            #pragma unroll
            for (int f = 0; f < F0; ++f) {
                float4 w4 = __ldg((const float4*)(wp + (size_t)f * wstride));
                // m-packed p operands, zero pack cost (LDS.128 -> u64 pairs)
                ulonglong2 pA = *(const ulonglong2*)&ps[f][mbase];      // {p0,p1},{p2,p3}
                ulonglong2 pB = *(const ulonglong2*)&ps[f][mbase + 4];  // {p4,p5},{p6,p7}
                unsigned long long wd0 = pkdup(w4.x);
                unsigned long long wd1 = pkdup(w4.y);
                unsigned long long wd2 = pkdup(w4.z);
                unsigned long long wd3 = pkdup(w4.w);
                fma2(acc[0][0], pA.x, wd0); fma2(acc[0][1], pA.x, wd1);
                fma2(acc[0][2], pA.x, wd2); fma2(acc[0][3], pA.x, wd3);
                fma2(acc[1][0], pA.y, wd0); fma2(acc[1][1], pA.y, wd1);
                fma2(acc[1][2], pA.y, wd2); fma2(acc[1][3], pA.y, wd3);
                fma2(acc[2][0], pB.x, wd0); fma2(acc[2][1], pB.x, wd1);
                fma2(acc[2][2], pB.x, wd2); fma2(acc[2][3], pB.x, wd3);
                fma2(acc[3][0], pB.y, wd0); fma2(acc[3][1], pB.y, wd1);
                fma2(acc[3][2], pB.y, wd2); fma2(acc[3][3], pB.y, wd3);
            }
        }

        // epilogue: bias + relu, write h for next layer, accumulate direct channels
        const float* bl = bs[layer];
        float4 bias4 = __ldg((const float4*)(bl + s0));
        float bias[4] = {bias4.x, bias4.y, bias4.z, bias4.w};
        float sums[4] = {0.f, 0.f, 0.f, 0.f};

        #pragma unroll
        for (int mp = 0; mp < 4; ++mp) {
            #pragma unroll
            for (int sq = 0; sq < 4; ++sq) {
                float2 vv = upk(acc[mp][sq]);
                vv.x = fmaxf(vv.x + bias[sq], 0.0f);
                vv.y = fmaxf(vv.y + bias[sq], 0.0f);
                sums[sq] += vv.x + vv.y;
                if (layer < 2 && s0 < 64) {
                    hs[mbase + 2 * mp + 0][s0 + sq] = vv.x;
                    hs[mbase + 2 * mp + 1][s0 + sq] = vv.y;
                }
            }
        }

        // direct-channel mapping into the concatenated result
        int ch = -1;
        if (layer == 0)      { if (s0 >= 64) ch = s0 - 64; }   // result ch 0..63
        else if (layer == 1) { if (s0 >= 64) ch = s0; }        // result ch 64..127
        else                 { ch = 128 + s0; }                // result ch 128..255
        if (ch >= 0) {
            #pragma unroll
            for (int sq = 0; sq < 4; ++sq)
                atomicAdd(&osum[b_loc][ch + sq], sums[sq]);
        }
        // next iteration's leading __syncthreads orders hs writes vs p-phase reads
    }

    __syncthreads();
    // write results: 4 b's x 256 channels
    const int bbase = pair0 >> 4;
    for (int i = tid; i < 4 * 256; i += NT) {
        int bl = i >> 8, ch = i & 255;
        out[(size_t)(bbase + bl) * 256 + ch] = osum[bl][ch];
    }
}

extern "C" void kernel_launch(void* const* d_in, const int* in_sizes, int n_in,
                              void* d_out, int out_size) {
    const float* x  = (const float*)d_in[0];
    const float* W0 = (const float*)d_in[1];
    const float* W1 = (const float*)d_in[2];
    const float* W2 = (const float*)d_in[3];
    const float* b0 = (const float*)d_in[4];
    const float* b1 = (const float*)d_in[5];
    const float* b2 = (const float*)d_in[6];
    float* out = (float*)d_out;

    const int pairs = 2048 * 16;
    cin_kernel<<<pairs / MTILE, NT>>>(x, W0, W1, W2, b0, b1, b2, out);
}